// round 9
// baseline (speedup 1.0000x reference)
#include <cuda_runtime.h>
#include <math.h>

#define DD    64
#define HH    128
#define WW    128
#define HW    (HH * WW)            // 16384
#define BC    128
#define CCH   64
#define SLAB  ((size_t)DD * HW)    // 1,048,576 per (b,c)
#define NTHR  128                  // 4 warps; warp = 8 output rows x full W
#define NCHUNK 4                   // H split into 4 chunks of 32 rows
#define CH_ROWS 32
#define ROW_F4 32                  // 32 float4 per 128-float row
#define WROWS  10                  // 8 output rows + 2 halo rows per warp tile
#define SLOT_F4 (WROWS * ROW_F4)   // 320 float4 per warp-plane slot
#define NSLOT  3                   // private ring of 3 plane slots per warp
#define WBUF_F4 (NSLOT * SLOT_F4)  // 960 float4 per warp
#define SMEM_BYTES (4 * WBUF_F4 * 16)  // 61440 B per CTA
#define NPART  (NCHUNK * 4)        // 16 per-warp partials per (b,c)

typedef unsigned long long u64;

__device__ float g_psum[BC * NPART];
__device__ float g_psq [BC * NPART];
__device__ float g_mean[BC];
__device__ float g_rstd[BC];

// ---- packed fp32x2 helpers ----
__device__ __forceinline__ u64 pk2(float lo, float hi) {
    u64 r;
    asm("mov.b64 %0, {%1, %2};" : "=l"(r)
        : "r"(__float_as_uint(lo)), "r"(__float_as_uint(hi)));
    return r;
}
__device__ __forceinline__ void upk2(u64 v, float& lo, float& hi) {
    unsigned int a, b;
    asm("mov.b64 {%0, %1}, %2;" : "=r"(a), "=r"(b) : "l"(v));
    lo = __uint_as_float(a); hi = __uint_as_float(b);
}
__device__ __forceinline__ void fma2i(u64& acc, u64 a, u64 b) {
    asm("fma.rn.f32x2 %0, %1, %2, %0;" : "+l"(acc) : "l"(a), "l"(b));
}
__device__ __forceinline__ u64 fma2o(u64 a, u64 b, u64 c) {
    u64 d;
    asm("fma.rn.f32x2 %0, %1, %2, %3;" : "=l"(d) : "l"(a), "l"(b), "l"(c));
    return d;
}
__device__ __forceinline__ void add2i(u64& acc, u64 a) {
    asm("add.rn.f32x2 %0, %1, %0;" : "+l"(acc) : "l"(a));
}
__device__ __forceinline__ void commit_g() {
    asm volatile("cp.async.commit_group;" ::: "memory");
}

// ---- warp-private plane-slot load: 10 rows, lane k loads float4 col k of each row.
// Every byte a thread later LDS-reads was cp.async'd (or STS-zeroed) by that same
// thread, so cp.async.wait_group alone orders it: NO CTA barrier needed, ever.
__device__ __forceinline__ void load_slot(const float* __restrict__ src_plane,
                                          int h0w, unsigned int sslot, int lane)
{
    const float* g = src_plane + (ptrdiff_t)h0w * WW + lane * 4;  // row 0 (may be OOB, never deref'd then)
    unsigned int sa = sslot + lane * 16;
    #pragma unroll
    for (int r = 0; r < WROWS; ++r) {
        const int h = h0w + r;                         // uniform per warp
        if ((unsigned)h < (unsigned)HH) {
            asm volatile("cp.async.cg.shared.global [%0], [%1], 16;"
                         :: "r"(sa + r * (ROW_F4 * 16)), "l"(g + r * WW));
        } else {
            asm volatile("st.shared.v4.b32 [%0], {%1,%1,%1,%1};"
                         :: "r"(sa + r * (ROW_F4 * 16)), "r"(0));   // H zero-pad
        }
    }
    commit_g();
}

// ---- one sweep over the warp's 10 private rows; 1 or 2 accumulator targets ----
template<int NT, int SA, int SB>
__device__ __forceinline__ void conv_pass(const float4* __restrict__ slot, int lane,
                                          const u64 (&Wp)[27], u64 (&A)[16], u64 (&B)[16])
{
    #pragma unroll
    for (int r = 0; r < WROWS; ++r) {
        float4 q = slot[r * ROW_F4 + lane];
        float left  = __shfl_up_sync(0xffffffffu, q.w, 1);
        float right = __shfl_down_sync(0xffffffffu, q.x, 1);
        if (lane == 0)  left  = 0.f;   // true W zero-pad
        if (lane == 31) right = 0.f;
        u64 pp[5];
        pp[0] = pk2(left, q.x);
        pp[1] = pk2(q.x,  q.y);
        pp[2] = pk2(q.y,  q.z);
        pp[3] = pk2(q.z,  q.w);
        pp[4] = pk2(q.w,  right);
        #pragma unroll
        for (int oo = 0; oo < 8; ++oo) {
            const int dy = r - 1 - oo + 1;             // = r - oo; tap index
            if (dy < 0 || dy > 2) continue;            // folds at compile time
            {
                const u64 w0 = Wp[SA * 9 + dy * 3 + 0];
                const u64 w1 = Wp[SA * 9 + dy * 3 + 1];
                const u64 w2 = Wp[SA * 9 + dy * 3 + 2];
                fma2i(A[oo * 2 + 0], pp[0], w0);
                fma2i(A[oo * 2 + 0], pp[1], w1);
                fma2i(A[oo * 2 + 0], pp[2], w2);
                fma2i(A[oo * 2 + 1], pp[2], w0);
                fma2i(A[oo * 2 + 1], pp[3], w1);
                fma2i(A[oo * 2 + 1], pp[4], w2);
            }
            if (NT == 2) {
                const u64 w0 = Wp[SB * 9 + dy * 3 + 0];
                const u64 w1 = Wp[SB * 9 + dy * 3 + 1];
                const u64 w2 = Wp[SB * 9 + dy * 3 + 2];
                fma2i(B[oo * 2 + 0], pp[0], w0);
                fma2i(B[oo * 2 + 0], pp[1], w1);
                fma2i(B[oo * 2 + 0], pp[2], w2);
                fma2i(B[oo * 2 + 1], pp[2], w0);
                fma2i(B[oo * 2 + 1], pp[3], w1);
                fma2i(B[oo * 2 + 1], pp[4], w2);
            }
        }
    }
}

// ---- finalize a completed output plane: stats (pass1) or normalize+relu+store (pass2) ----
template<int PASS>
__device__ __forceinline__ void finalize(u64 (&A)[16], int d, u64& s2, u64& q2,
                                         u64 gsc2, u64 bsc2, float* __restrict__ outp)
{
    if (PASS == 1) {
        #pragma unroll
        for (int i = 0; i < 16; ++i) { add2i(s2, A[i]); fma2i(q2, A[i], A[i]); }
    } else {
        float* os = outp + (size_t)d * HW;
        #pragma unroll
        for (int oo = 0; oo < 8; ++oo) {
            u64 ya = fma2o(A[oo * 2 + 0], gsc2, bsc2);
            u64 yb = fma2o(A[oo * 2 + 1], gsc2, bsc2);
            float a0, a1, a2, a3;
            upk2(ya, a0, a1); upk2(yb, a2, a3);
            float4 r4;
            r4.x = fmaxf(a0, 0.f); r4.y = fmaxf(a1, 0.f);
            r4.z = fmaxf(a2, 0.f); r4.w = fmaxf(a3, 0.f);
            *(float4*)(os + oo * WW) = r4;
        }
    }
}

// ---- one z-step (slot is compile-time): wait plane z, two sweeps, retire out[z-1],
//      then prefetch plane z+3 into this same slot (read-then-write, own-thread order).
template<int PASS, int SLOT>
__device__ __forceinline__ void full_step(int z, const float* __restrict__ xs,
        const float4* __restrict__ wbuf, unsigned int swbuf, int h0w, int lane,
        const u64 (&Wp)[27], u64 (&O)[16], u64 (&N)[16],
        u64& s2, u64& q2, u64 gsc2, u64 bsc2, float* __restrict__ outp)
{
    asm volatile("cp.async.wait_group 2;" ::: "memory");  // plane z resident (own data)
    const float4* slot = wbuf + SLOT * SLOT_F4;
    conv_pass<2, 2, 1>(slot, lane, Wp, O, N);   // O=out[z-1]+=W2, N=out[z]+=W1
    finalize<PASS>(O, z - 1, s2, q2, gsc2, bsc2, outp);
    #pragma unroll
    for (int i = 0; i < 16; ++i) O[i] = 0ull;
    conv_pass<1, 0, 0>(slot, lane, Wp, O, O);   // O = W0 contribution to out[z+1]
    const int zp = z + 3;                        // (z+3)%3 == SLOT
    if (zp < DD) load_slot(xs + (size_t)zp * HW, h0w, swbuf + SLOT * (SLOT_F4 * 16), lane);
    else         commit_g();                     // keep pending-group invariant
}

// PASS 1: streaming conv + per-WARP (sum,sumsq) to global. PASS 2: conv+norm+relu+store.
// NO __syncthreads anywhere: warp-private smem tiles, own-thread cp.async ordering.
template<int PASS>
__global__ void __launch_bounds__(NTHR, 3)
conv_stream_kernel(const float* __restrict__ x, const float* __restrict__ wt,
                   const float* __restrict__ gamma, const float* __restrict__ beta,
                   float* __restrict__ out)
{
    extern __shared__ float4 smem4[];
    const int hc = blockIdx.x;
    const int bc = blockIdx.y;
    const int c  = bc & (CCH - 1);
    const int tid  = threadIdx.x;
    const int lane = tid & 31;
    const int warp = tid >> 5;
    const int h0w  = hc * CH_ROWS + warp * 8 - 1;   // global h of warp-tile row 0
    const float* xs = x + (size_t)bc * SLAB;

    float4* wbuf = smem4 + warp * WBUF_F4;          // warp-private ring (3 slots)
    unsigned int swbuf = (unsigned int)__cvta_generic_to_shared(wbuf);

    u64 Wp[27];
    #pragma unroll
    for (int i = 0; i < 27; ++i) { float wv = __ldg(wt + c * 27 + i); Wp[i] = pk2(wv, wv); }

    u64 gsc2 = 0, bsc2 = 0;
    float* outp = out + (size_t)bc * SLAB + (size_t)(h0w + 1) * WW + lane * 4;
    if (PASS == 2) {
        const float rstd = g_rstd[bc], mean = g_mean[bc];
        const float gsc = gamma[c] * rstd;
        const float bsc = fmaf(-mean, gsc, beta[c]);
        gsc2 = pk2(gsc, gsc);
        bsc2 = pk2(bsc, bsc);
    }

    // prologue: planes 0,1,2 into private slots 0,1,2
    load_slot(xs,                     h0w, swbuf,                     lane);
    load_slot(xs + (size_t)1 * HW,    h0w, swbuf + 1 * (SLOT_F4*16),  lane);
    load_slot(xs + (size_t)2 * HW,    h0w, swbuf + 2 * (SLOT_F4*16),  lane);

    u64 P[16], Q[16];
    #pragma unroll
    for (int i = 0; i < 16; ++i) { P[i] = 0ull; Q[i] = 0ull; }
    u64 s2 = 0ull, q2 = 0ull;

    // z=0 (slot 0; plane -1 is zero): Q=out[0]+=W1, P=out[1]=W0; then prefetch plane 3
    asm volatile("cp.async.wait_group 2;" ::: "memory");
    conv_pass<2, 1, 0>(wbuf, lane, Wp, Q, P);
    load_slot(xs + (size_t)3 * HW, h0w, swbuf, lane);

    // z = 1..60: period-6 unroll (role swap period 2 x slot period 3), all compile-time
    for (int t = 0; t < 10; ++t) {
        const int z = 6 * t;
        full_step<PASS, 1>(z + 1, xs, wbuf, swbuf, h0w, lane, Wp, Q, P, s2, q2, gsc2, bsc2, outp);
        full_step<PASS, 2>(z + 2, xs, wbuf, swbuf, h0w, lane, Wp, P, Q, s2, q2, gsc2, bsc2, outp);
        full_step<PASS, 0>(z + 3, xs, wbuf, swbuf, h0w, lane, Wp, Q, P, s2, q2, gsc2, bsc2, outp);
        full_step<PASS, 1>(z + 4, xs, wbuf, swbuf, h0w, lane, Wp, P, Q, s2, q2, gsc2, bsc2, outp);
        full_step<PASS, 2>(z + 5, xs, wbuf, swbuf, h0w, lane, Wp, Q, P, s2, q2, gsc2, bsc2, outp);
        full_step<PASS, 0>(z + 6, xs, wbuf, swbuf, h0w, lane, Wp, P, Q, s2, q2, gsc2, bsc2, outp);
    }
    full_step<PASS, 1>(61, xs, wbuf, swbuf, h0w, lane, Wp, Q, P, s2, q2, gsc2, bsc2, outp);
    full_step<PASS, 2>(62, xs, wbuf, swbuf, h0w, lane, Wp, P, Q, s2, q2, gsc2, bsc2, outp);

    // z=63 (slot 0; plane 64 is zero): Q=out[62]+=W2, P=out[63]+=W1; both complete
    asm volatile("cp.async.wait_group 0;" ::: "memory");
    conv_pass<2, 2, 1>(wbuf, lane, Wp, Q, P);
    finalize<PASS>(Q, 62, s2, q2, gsc2, bsc2, outp);
    finalize<PASS>(P, 63, s2, q2, gsc2, bsc2, outp);

    if (PASS == 1) {
        float sl, sh, ql, qh;
        upk2(s2, sl, sh); upk2(q2, ql, qh);
        float s = sl + sh, q = ql + qh;
        #pragma unroll
        for (int off = 16; off > 0; off >>= 1) {
            s += __shfl_down_sync(0xffffffffu, s, off);
            q += __shfl_down_sync(0xffffffffu, q, off);
        }
        if (lane == 0) {                       // per-warp partial straight to global
            g_psum[bc * NPART + hc * 4 + warp] = s;
            g_psq [bc * NPART + hc * 4 + warp] = q;
        }
    }
}

__global__ void finalize_stats_kernel()
{
    const int bc = threadIdx.x;
    if (bc >= BC) return;
    double s = 0.0, q = 0.0;
    #pragma unroll
    for (int j = 0; j < NPART; ++j) {
        s += (double)g_psum[bc * NPART + j];
        q += (double)g_psq [bc * NPART + j];
    }
    const double n = (double)SLAB;
    const double mean = s / n;
    const double var  = q / n - mean * mean;
    g_mean[bc] = (float)mean;
    g_rstd[bc] = (float)(1.0 / sqrt(var + 1e-5));
}

extern "C" void kernel_launch(void* const* d_in, const int* in_sizes, int n_in,
                              void* d_out, int out_size)
{
    (void)in_sizes; (void)n_in; (void)out_size;
    const float* x     = (const float*)d_in[0];
    const float* w     = (const float*)d_in[1];
    const float* gamma = (const float*)d_in[2];
    const float* beta  = (const float*)d_in[3];
    float* out = (float*)d_out;

    cudaFuncSetAttribute(conv_stream_kernel<1>,
                         cudaFuncAttributeMaxDynamicSharedMemorySize, SMEM_BYTES);
    cudaFuncSetAttribute(conv_stream_kernel<2>,
                         cudaFuncAttributeMaxDynamicSharedMemorySize, SMEM_BYTES);

    dim3 grid(NCHUNK, BC);  // 512 CTAs of 128 threads, 3 CTAs/SM (smem 60KB)
    conv_stream_kernel<1><<<grid, NTHR, SMEM_BYTES>>>(x, w, gamma, beta, out);
    finalize_stats_kernel<<<1, BC>>>();
    conv_stream_kernel<2><<<grid, NTHR, SMEM_BYTES>>>(x, w, gamma, beta, out);
}

// round 12
// speedup vs baseline: 1.8254x; 1.8254x over previous
#include <cuda_runtime.h>
#include <math.h>

#define DD    64
#define HH    128
#define WW    128
#define HW    (HH * WW)            // 16384
#define BC    128
#define CCH   64
#define SLAB  ((size_t)DD * HW)    // 1,048,576 per (b,c)
#define NTHR  128                  // 4 warps; warp covers W=128 (float4/lane), 8 rows
#define NCHUNK 4                   // H split into 4 chunks of 32 rows
#define CH_ROWS 32
#define LROWS 34                   // 32 output rows + 2 halo rows
#define ROW_F4 (WW / 4)            // 32 float4 per row
#define PLANE_F4 (LROWS * ROW_F4)  // 1088 float4 per tile-plane
#define SMEM_BYTES (3 * PLANE_F4 * 16)  // 52224 B (3-buffer ring)

typedef unsigned long long u64;

__device__ float g_psum[BC * NCHUNK];
__device__ float g_psq [BC * NCHUNK];
__device__ float g_mean[BC];
__device__ float g_rstd[BC];

// ---- packed fp32x2 helpers (Blackwell f32x2 pipe: 2x FFMA throughput vs 3-reg FFMA) ----
__device__ __forceinline__ u64 pk2(float lo, float hi) {
    u64 r;
    asm("mov.b64 %0, {%1, %2};" : "=l"(r)
        : "r"(__float_as_uint(lo)), "r"(__float_as_uint(hi)));
    return r;
}
__device__ __forceinline__ void upk2(u64 v, float& lo, float& hi) {
    unsigned int a, b;
    asm("mov.b64 {%0, %1}, %2;" : "=r"(a), "=r"(b) : "l"(v));
    lo = __uint_as_float(a); hi = __uint_as_float(b);
}
__device__ __forceinline__ void fma2i(u64& acc, u64 a, u64 b) {
    asm("fma.rn.f32x2 %0, %1, %2, %0;" : "+l"(acc) : "l"(a), "l"(b));
}
__device__ __forceinline__ u64 fma2o(u64 a, u64 b, u64 c) {
    u64 d;
    asm("fma.rn.f32x2 %0, %1, %2, %3;" : "=l"(d) : "l"(a), "l"(b), "l"(c));
    return d;
}
__device__ __forceinline__ void add2i(u64& acc, u64 a) {
    asm("add.rn.f32x2 %0, %1, %0;" : "+l"(acc) : "l"(a));
}

// ---- async tile-plane load: 34 rows x 128 cols, zero-filled at H edges ----
__device__ __forceinline__ void load_plane(const float* __restrict__ xs, int z, int h0,
                                           float4* __restrict__ buf, int tid)
{
    const float* src = xs + (size_t)z * HW;
    unsigned int sbase = (unsigned int)__cvta_generic_to_shared(buf);
    #pragma unroll
    for (int it = 0; it < 9; ++it) {
        int i = tid + it * NTHR;
        if (it < 8 || i < PLANE_F4) {
            int row = i >> 5;
            int c4  = i & 31;
            int h   = h0 - 1 + row;
            if ((unsigned)h < (unsigned)HH) {
                const float* g = src + h * WW + c4 * 4;
                unsigned int sa = sbase + i * 16;
                asm volatile("cp.async.cg.shared.global [%0], [%1], 16;"
                             :: "r"(sa), "l"(g));
            } else {
                buf[i] = make_float4(0.f, 0.f, 0.f, 0.f);  // H zero-pad
            }
        }
    }
}
__device__ __forceinline__ void commit_g() {
    asm volatile("cp.async.commit_group;" ::: "memory");
}

// ---- one sweep over the 10 smem rows a warp needs; updates 1 or 2 acc targets ----
template<int NT, int SA, int SB>
__device__ __forceinline__ void conv_pass(const float4* __restrict__ buf, int olb, int lane,
                                          const u64 (&Wp)[27], u64 (&A)[16], u64 (&B)[16])
{
    #pragma unroll
    for (int r = 0; r < 10; ++r) {
        float4 q = buf[(olb + r) * ROW_F4 + lane];
        float left  = __shfl_up_sync(0xffffffffu, q.w, 1);
        float right = __shfl_down_sync(0xffffffffu, q.x, 1);
        if (lane == 0)  left  = 0.f;   // true W zero-pad
        if (lane == 31) right = 0.f;
        u64 pp[5];
        pp[0] = pk2(left, q.x);
        pp[1] = pk2(q.x,  q.y);
        pp[2] = pk2(q.y,  q.z);
        pp[3] = pk2(q.z,  q.w);
        pp[4] = pk2(q.w,  right);
        #pragma unroll
        for (int oo = 0; oo < 8; ++oo) {
            const int dy = r - oo;
            if (dy < 0 || dy > 2) continue;      // folds at compile time
            {
                const u64 w0 = Wp[SA * 9 + dy * 3 + 0];
                const u64 w1 = Wp[SA * 9 + dy * 3 + 1];
                const u64 w2 = Wp[SA * 9 + dy * 3 + 2];
                fma2i(A[oo * 2 + 0], pp[0], w0);
                fma2i(A[oo * 2 + 0], pp[1], w1);
                fma2i(A[oo * 2 + 0], pp[2], w2);
                fma2i(A[oo * 2 + 1], pp[2], w0);
                fma2i(A[oo * 2 + 1], pp[3], w1);
                fma2i(A[oo * 2 + 1], pp[4], w2);
            }
            if (NT == 2) {
                const u64 w0 = Wp[SB * 9 + dy * 3 + 0];
                const u64 w1 = Wp[SB * 9 + dy * 3 + 1];
                const u64 w2 = Wp[SB * 9 + dy * 3 + 2];
                fma2i(B[oo * 2 + 0], pp[0], w0);
                fma2i(B[oo * 2 + 0], pp[1], w1);
                fma2i(B[oo * 2 + 0], pp[2], w2);
                fma2i(B[oo * 2 + 1], pp[2], w0);
                fma2i(B[oo * 2 + 1], pp[3], w1);
                fma2i(B[oo * 2 + 1], pp[4], w2);
            }
        }
    }
}

// ---- finalize a completed output plane: stats (pass1) or normalize+relu+store (pass2) ----
template<int PASS>
__device__ __forceinline__ void finalize(u64 (&A)[16], int d, u64& s2, u64& q2,
                                         u64 gsc2, u64 bsc2, float* __restrict__ outp)
{
    if (PASS == 1) {
        #pragma unroll
        for (int i = 0; i < 16; ++i) { add2i(s2, A[i]); fma2i(q2, A[i], A[i]); }
    } else {
        float* os = outp + (size_t)d * HW;
        #pragma unroll
        for (int oo = 0; oo < 8; ++oo) {
            u64 ya = fma2o(A[oo * 2 + 0], gsc2, bsc2);
            u64 yb = fma2o(A[oo * 2 + 1], gsc2, bsc2);
            float a0, a1, a2, a3;
            upk2(ya, a0, a1); upk2(yb, a2, a3);
            float4 r4;
            r4.x = fmaxf(a0, 0.f); r4.y = fmaxf(a1, 0.f);
            r4.z = fmaxf(a2, 0.f); r4.w = fmaxf(a3, 0.f);
            *(float4*)(os + oo * WW) = r4;
        }
    }
}

template<int PASS>
__device__ __forceinline__ void full_step(int z, const float* __restrict__ xs,
        float4* __restrict__ smem4, int h0, int tid, int olb, int lane,
        const u64 (&Wp)[27], u64 (&O)[16], u64 (&N)[16],
        u64& s2, u64& q2, u64 gsc2, u64 bsc2, float* __restrict__ outp)
{
    asm volatile("cp.async.wait_group 1;" ::: "memory");  // plane z resident
    __syncthreads();
    const int zp = z + 2;
    if (zp < DD) load_plane(xs, zp, h0, smem4 + (zp % 3) * PLANE_F4, tid);
    commit_g();  // one group per step (possibly empty) keeps the count invariant
    const float4* buf = smem4 + (z % 3) * PLANE_F4;
    conv_pass<2, 2, 1>(buf, olb, lane, Wp, O, N);   // O=out[z-1]+=W2, N=out[z]+=W1
    finalize<PASS>(O, z - 1, s2, q2, gsc2, bsc2, outp);
    #pragma unroll
    for (int i = 0; i < 16; ++i) O[i] = 0ull;
    conv_pass<1, 0, 0>(buf, olb, lane, Wp, O, O);   // O=out[z+1] = W0 contribution
}

// PASS 1: streaming conv + per-CTA (sum, sumsq).  PASS 2: conv + norm + relu + store.
// Identical to the 387us R6 kernel except __launch_bounds__(128, 4): caps regs at 128
// so 4 CTAs/SM fit the 64K regfile; smem 4 x 52224B = 204KB fits the 228KB carveout.
template<int PASS>
__global__ void __launch_bounds__(NTHR, 4)
conv_stream_kernel(const float* __restrict__ x, const float* __restrict__ wt,
                   const float* __restrict__ gamma, const float* __restrict__ beta,
                   float* __restrict__ out)
{
    extern __shared__ float4 smem4[];
    const int hc = blockIdx.x;
    const int bc = blockIdx.y;
    const int c  = bc & (CCH - 1);
    const int h0 = hc * CH_ROWS;
    const int tid  = threadIdx.x;
    const int lane = tid & 31;
    const int olb  = (tid >> 5) * 8;               // warp's 8 output rows within the chunk
    const float* xs = x + (size_t)bc * SLAB;

    u64 Wp[27];
    #pragma unroll
    for (int i = 0; i < 27; ++i) { float wv = __ldg(wt + c * 27 + i); Wp[i] = pk2(wv, wv); }

    u64 gsc2 = 0, bsc2 = 0;
    float* outp = out + (size_t)bc * SLAB + (size_t)(h0 + olb) * WW + lane * 4;
    if (PASS == 2) {
        const float rstd = g_rstd[bc], mean = g_mean[bc];
        const float gsc = gamma[c] * rstd;
        const float bsc = fmaf(-mean, gsc, beta[c]);
        gsc2 = pk2(gsc, gsc);
        bsc2 = pk2(bsc, bsc);
    }

    // pipeline prologue: planes 0 and 1 in flight
    load_plane(xs, 0, h0, smem4,            tid); commit_g();
    load_plane(xs, 1, h0, smem4 + PLANE_F4, tid); commit_g();

    u64 P[16], Q[16];
    #pragma unroll
    for (int i = 0; i < 16; ++i) { P[i] = 0ull; Q[i] = 0ull; }
    u64 s2 = 0ull, q2 = 0ull;  // bits of (0.f, 0.f)

    // z = 0 (plane -1 is zero -> no W2 target yet): Q=out[0]+=W1, P=out[1]=W0
    asm volatile("cp.async.wait_group 1;" ::: "memory");
    __syncthreads();
    load_plane(xs, 2, h0, smem4 + 2 * PLANE_F4, tid); commit_g();
    conv_pass<2, 1, 0>(smem4, olb, lane, Wp, Q, P);

    for (int zz = 1; zz < 63; zz += 2) {
        full_step<PASS>(zz,     xs, smem4, h0, tid, olb, lane, Wp, Q, P, s2, q2, gsc2, bsc2, outp);
        full_step<PASS>(zz + 1, xs, smem4, h0, tid, olb, lane, Wp, P, Q, s2, q2, gsc2, bsc2, outp);
    }

    // z = 63 (plane 64 is zero): Q=out[62]+=W2, P=out[63]+=W1; both complete
    asm volatile("cp.async.wait_group 0;" ::: "memory");
    __syncthreads();
    conv_pass<2, 2, 1>(smem4 + (63 % 3) * PLANE_F4, olb, lane, Wp, Q, P);
    finalize<PASS>(Q, 62, s2, q2, gsc2, bsc2, outp);
    finalize<PASS>(P, 63, s2, q2, gsc2, bsc2, outp);

    if (PASS == 1) {
        float sl, sh, ql, qh;
        upk2(s2, sl, sh); upk2(q2, ql, qh);
        float s = sl + sh, q = ql + qh;
        #pragma unroll
        for (int off = 16; off > 0; off >>= 1) {
            s += __shfl_down_sync(0xffffffffu, s, off);
            q += __shfl_down_sync(0xffffffffu, q, off);
        }
        __syncthreads();                 // compute done; smem reusable
        float* red = (float*)smem4;
        const int warp = tid >> 5;
        if (lane == 0) { red[warp] = s; red[8 + warp] = q; }
        __syncthreads();
        if (tid == 0) {
            g_psum[bc * NCHUNK + hc] = red[0] + red[1] + red[2] + red[3];
            g_psq [bc * NCHUNK + hc] = red[8] + red[9] + red[10] + red[11];
        }
    }
}

__global__ void finalize_stats_kernel()
{
    const int bc = threadIdx.x;
    if (bc >= BC) return;
    double s = 0.0, q = 0.0;
    #pragma unroll
    for (int j = 0; j < NCHUNK; ++j) {
        s += (double)g_psum[bc * NCHUNK + j];
        q += (double)g_psq [bc * NCHUNK + j];
    }
    const double n = (double)SLAB;
    const double mean = s / n;
    const double var  = q / n - mean * mean;
    g_mean[bc] = (float)mean;
    g_rstd[bc] = (float)(1.0 / sqrt(var + 1e-5));
}

extern "C" void kernel_launch(void* const* d_in, const int* in_sizes, int n_in,
                              void* d_out, int out_size)
{
    (void)in_sizes; (void)n_in; (void)out_size;
    const float* x     = (const float*)d_in[0];
    const float* w     = (const float*)d_in[1];
    const float* gamma = (const float*)d_in[2];
    const float* beta  = (const float*)d_in[3];
    float* out = (float*)d_out;

    cudaFuncSetAttribute(conv_stream_kernel<1>,
                         cudaFuncAttributeMaxDynamicSharedMemorySize, SMEM_BYTES);
    cudaFuncSetAttribute(conv_stream_kernel<2>,
                         cudaFuncAttributeMaxDynamicSharedMemorySize, SMEM_BYTES);

    dim3 grid(NCHUNK, BC);  // 512 CTAs of 128 threads; target 4 CTAs/SM
    conv_stream_kernel<1><<<grid, NTHR, SMEM_BYTES>>>(x, w, gamma, beta, out);
    finalize_stats_kernel<<<1, BC>>>();
    conv_stream_kernel<2><<<grid, NTHR, SMEM_BYTES>>>(x, w, gamma, beta, out);
}

// round 13
// speedup vs baseline: 2.0062x; 1.0991x over previous
#include <cuda_runtime.h>
#include <math.h>

#define DD    64
#define HH    128
#define WW    128
#define HW    (HH * WW)            // 16384
#define BC    128
#define CCH   64
#define SLAB  ((size_t)DD * HW)    // 1,048,576 per (b,c)
#define NTHR  128                  // 4 warps; warp = 4 output rows x full W
#define NCHUNK 8                   // H split into 8 chunks of 16 rows
#define CH_ROWS 16
#define LROWS 18                   // 16 output rows + 2 halo rows
#define ROW_F4 (WW / 4)            // 32 float4 per row
#define PLANE_F4 (LROWS * ROW_F4)  // 576 float4 per tile-plane
#define SMEM_BYTES (3 * PLANE_F4 * 16)  // 27648 B (3-slot ring)

typedef unsigned long long u64;

__device__ float g_psum[BC * NCHUNK];
__device__ float g_psq [BC * NCHUNK];
__device__ float g_mean[BC];
__device__ float g_rstd[BC];

// ---- packed fp32x2 helpers ----
__device__ __forceinline__ u64 pk2(float lo, float hi) {
    u64 r;
    asm("mov.b64 %0, {%1, %2};" : "=l"(r)
        : "r"(__float_as_uint(lo)), "r"(__float_as_uint(hi)));
    return r;
}
__device__ __forceinline__ void upk2(u64 v, float& lo, float& hi) {
    unsigned int a, b;
    asm("mov.b64 {%0, %1}, %2;" : "=r"(a), "=r"(b) : "l"(v));
    lo = __uint_as_float(a); hi = __uint_as_float(b);
}
__device__ __forceinline__ void fma2i(u64& acc, u64 a, u64 b) {
    asm("fma.rn.f32x2 %0, %1, %2, %0;" : "+l"(acc) : "l"(a), "l"(b));
}
__device__ __forceinline__ u64 fma2o(u64 a, u64 b, u64 c) {
    u64 d;
    asm("fma.rn.f32x2 %0, %1, %2, %3;" : "=l"(d) : "l"(a), "l"(b), "l"(c));
    return d;
}
__device__ __forceinline__ void add2i(u64& acc, u64 a) {
    asm("add.rn.f32x2 %0, %1, %0;" : "+l"(acc) : "l"(a));
}
__device__ __forceinline__ void commit_g() {
    asm volatile("cp.async.commit_group;" ::: "memory");
}

// ---- async tile-plane load: 18 rows x 128 cols, zero-filled at H edges ----
__device__ __forceinline__ void load_plane(const float* __restrict__ xs, int z, int h0,
                                           float4* __restrict__ buf, int tid)
{
    const float* src = xs + (size_t)z * HW;
    unsigned int sbase = (unsigned int)__cvta_generic_to_shared(buf);
    #pragma unroll
    for (int it = 0; it < 5; ++it) {                 // 576 f4 / 128 thr = 4.5
        int i = tid + it * NTHR;
        if (it < 4 || i < PLANE_F4) {
            int row = i >> 5;
            int c4  = i & 31;
            int h   = h0 - 1 + row;
            if ((unsigned)h < (unsigned)HH) {
                const float* g = src + h * WW + c4 * 4;
                unsigned int sa = sbase + i * 16;
                asm volatile("cp.async.cg.shared.global [%0], [%1], 16;"
                             :: "r"(sa), "l"(g));
            } else {
                buf[i] = make_float4(0.f, 0.f, 0.f, 0.f);  // H zero-pad
            }
        }
    }
}

// ---- ONE sweep over the warp's 6 smem rows feeding up to THREE targets ----
// O += W(dz=2)*plane (completes out[z-1]); N += W(dz=1)*plane; F += W(dz=0)*plane (fresh).
template<bool HO, bool HF>
__device__ __forceinline__ void conv3(const float4* __restrict__ buf, int olb, int lane,
    const u64 (&W2p)[9], const u64 (&W1p)[9], const u64 (&W0p)[9],
    u64 (&O)[8], u64 (&N)[8], u64 (&F)[8])
{
    #pragma unroll
    for (int r = 0; r < 6; ++r) {
        float4 q = buf[(olb + r) * ROW_F4 + lane];
        float left  = __shfl_up_sync(0xffffffffu, q.w, 1);
        float right = __shfl_down_sync(0xffffffffu, q.x, 1);
        if (lane == 0)  left  = 0.f;   // true W zero-pad
        if (lane == 31) right = 0.f;
        u64 pp[5];
        pp[0] = pk2(left, q.x);
        pp[1] = pk2(q.x,  q.y);
        pp[2] = pk2(q.y,  q.z);
        pp[3] = pk2(q.z,  q.w);
        pp[4] = pk2(q.w,  right);
        #pragma unroll
        for (int oo = 0; oo < 4; ++oo) {
            const int dy = r - oo;                   // tap index; folds at compile time
            if (dy < 0 || dy > 2) continue;
            if (HO) {
                const u64 w0 = W2p[dy * 3 + 0], w1 = W2p[dy * 3 + 1], w2 = W2p[dy * 3 + 2];
                fma2i(O[oo * 2 + 0], pp[0], w0);
                fma2i(O[oo * 2 + 0], pp[1], w1);
                fma2i(O[oo * 2 + 0], pp[2], w2);
                fma2i(O[oo * 2 + 1], pp[2], w0);
                fma2i(O[oo * 2 + 1], pp[3], w1);
                fma2i(O[oo * 2 + 1], pp[4], w2);
            }
            {
                const u64 w0 = W1p[dy * 3 + 0], w1 = W1p[dy * 3 + 1], w2 = W1p[dy * 3 + 2];
                fma2i(N[oo * 2 + 0], pp[0], w0);
                fma2i(N[oo * 2 + 0], pp[1], w1);
                fma2i(N[oo * 2 + 0], pp[2], w2);
                fma2i(N[oo * 2 + 1], pp[2], w0);
                fma2i(N[oo * 2 + 1], pp[3], w1);
                fma2i(N[oo * 2 + 1], pp[4], w2);
            }
            if (HF) {
                const u64 w0 = W0p[dy * 3 + 0], w1 = W0p[dy * 3 + 1], w2 = W0p[dy * 3 + 2];
                fma2i(F[oo * 2 + 0], pp[0], w0);
                fma2i(F[oo * 2 + 0], pp[1], w1);
                fma2i(F[oo * 2 + 0], pp[2], w2);
                fma2i(F[oo * 2 + 1], pp[2], w0);
                fma2i(F[oo * 2 + 1], pp[3], w1);
                fma2i(F[oo * 2 + 1], pp[4], w2);
            }
        }
    }
}

// ---- finalize a completed output plane: stats (pass1) or normalize+relu+store (pass2) ----
template<int PASS>
__device__ __forceinline__ void finalize(u64 (&A)[8], int d, u64& s2, u64& q2,
                                         u64 gsc2, u64 bsc2, float* __restrict__ outp)
{
    if (PASS == 1) {
        #pragma unroll
        for (int i = 0; i < 8; ++i) { add2i(s2, A[i]); fma2i(q2, A[i], A[i]); }
    } else {
        float* os = outp + (size_t)d * HW;
        #pragma unroll
        for (int oo = 0; oo < 4; ++oo) {
            u64 ya = fma2o(A[oo * 2 + 0], gsc2, bsc2);
            u64 yb = fma2o(A[oo * 2 + 1], gsc2, bsc2);
            float a0, a1, a2, a3;
            upk2(ya, a0, a1); upk2(yb, a2, a3);
            float4 r4;
            r4.x = fmaxf(a0, 0.f); r4.y = fmaxf(a1, 0.f);
            r4.z = fmaxf(a2, 0.f); r4.w = fmaxf(a3, 0.f);
            *(float4*)(os + oo * WW) = r4;
        }
    }
}

// ---- one z-step, slots compile-time. R6-proven flow: wait plane z (1 outstanding),
// barrier (protects slot PSLOT = plane z-1's slot), prefetch z+2 into PSLOT, sweep, retire.
template<int PASS, int SLOT, int PSLOT>
__device__ __forceinline__ void step3(int z, const float* __restrict__ xs,
        float4* __restrict__ smem4, int h0, int tid, int olb, int lane,
        const u64 (&W2p)[9], const u64 (&W1p)[9], const u64 (&W0p)[9],
        u64 (&O)[8], u64 (&N)[8], u64 (&F)[8],
        u64& s2, u64& q2, u64 gsc2, u64 bsc2, float* __restrict__ outp)
{
    asm volatile("cp.async.wait_group 1;" ::: "memory");  // plane z resident
    __syncthreads();                                      // all warps done with plane z-1
    const int zp = z + 2;
    if (zp < DD) load_plane(xs, zp, h0, smem4 + PSLOT * PLANE_F4, tid);
    commit_g();  // one group per step (possibly empty) keeps the count invariant
    conv3<true, true>(smem4 + SLOT * PLANE_F4, olb, lane, W2p, W1p, W0p, O, N, F);
    finalize<PASS>(O, z - 1, s2, q2, gsc2, bsc2, outp);
    #pragma unroll
    for (int i = 0; i < 8; ++i) O[i] = 0ull;              // O becomes next step's fresh F
}

// PASS 1: streaming conv + per-CTA (sum,sumsq).  PASS 2: conv + norm + relu + store.
template<int PASS>
__global__ void __launch_bounds__(NTHR, 4)
conv_stream_kernel(const float* __restrict__ x, const float* __restrict__ wt,
                   const float* __restrict__ gamma, const float* __restrict__ beta,
                   float* __restrict__ out)
{
    extern __shared__ float4 smem4[];
    const int hc = blockIdx.x;
    const int bc = blockIdx.y;
    const int c  = bc & (CCH - 1);
    const int h0 = hc * CH_ROWS;
    const int tid  = threadIdx.x;
    const int lane = tid & 31;
    const int olb  = (tid >> 5) * 4;               // warp's 4 output rows within the chunk
    const float* xs = x + (size_t)bc * SLAB;

    u64 W2p[9], W1p[9], W0p[9];
    #pragma unroll
    for (int i = 0; i < 9; ++i) {
        float w0 = __ldg(wt + c * 27 + 0 * 9 + i);
        float w1 = __ldg(wt + c * 27 + 1 * 9 + i);
        float w2 = __ldg(wt + c * 27 + 2 * 9 + i);
        W0p[i] = pk2(w0, w0);
        W1p[i] = pk2(w1, w1);
        W2p[i] = pk2(w2, w2);
    }

    u64 gsc2 = 0, bsc2 = 0;
    float* outp = out + (size_t)bc * SLAB + (size_t)(h0 + olb) * WW + lane * 4;
    if (PASS == 2) {
        const float rstd = g_rstd[bc], mean = g_mean[bc];
        const float gsc = gamma[c] * rstd;
        const float bsc = fmaf(-mean, gsc, beta[c]);
        gsc2 = pk2(gsc, gsc);
        bsc2 = pk2(bsc, bsc);
    }

    // prologue: planes 0,1 in flight (slots 0,1)
    load_plane(xs, 0, h0, smem4,            tid); commit_g();
    load_plane(xs, 1, h0, smem4 + PLANE_F4, tid); commit_g();

    u64 A0[8], A1[8], A2[8];
    #pragma unroll
    for (int i = 0; i < 8; ++i) { A0[i] = 0ull; A1[i] = 0ull; A2[i] = 0ull; }
    u64 s2 = 0ull, q2 = 0ull;

    // z = 0 (slot 0; plane -1 is zero -> no O target): N=A0 (out[0], W1), F=A1 (out[1], W0)
    asm volatile("cp.async.wait_group 1;" ::: "memory");
    __syncthreads();
    load_plane(xs, 2, h0, smem4 + 2 * PLANE_F4, tid); commit_g();
    conv3<false, true>(smem4, olb, lane, W2p, W1p, W0p, A2, A0, A1);

    // z = 1..60: slot = z%3, roles rotate with the same period-3 -> all compile-time
    for (int t = 0; t < 20; ++t) {
        const int z = 3 * t;
        step3<PASS, 1, 0>(z + 1, xs, smem4, h0, tid, olb, lane, W2p, W1p, W0p,
                          A0, A1, A2, s2, q2, gsc2, bsc2, outp);
        step3<PASS, 2, 1>(z + 2, xs, smem4, h0, tid, olb, lane, W2p, W1p, W0p,
                          A1, A2, A0, s2, q2, gsc2, bsc2, outp);
        step3<PASS, 0, 2>(z + 3, xs, smem4, h0, tid, olb, lane, W2p, W1p, W0p,
                          A2, A0, A1, s2, q2, gsc2, bsc2, outp);
    }
    step3<PASS, 1, 0>(61, xs, smem4, h0, tid, olb, lane, W2p, W1p, W0p,
                      A0, A1, A2, s2, q2, gsc2, bsc2, outp);
    step3<PASS, 2, 1>(62, xs, smem4, h0, tid, olb, lane, W2p, W1p, W0p,
                      A1, A2, A0, s2, q2, gsc2, bsc2, outp);

    // z = 63 (slot 0; plane 64 is zero -> no F): O=A2 (out[62]), N=A0 (out[63])
    asm volatile("cp.async.wait_group 0;" ::: "memory");
    __syncthreads();
    conv3<true, false>(smem4, olb, lane, W2p, W1p, W0p, A2, A0, A1);
    finalize<PASS>(A2, 62, s2, q2, gsc2, bsc2, outp);
    finalize<PASS>(A0, 63, s2, q2, gsc2, bsc2, outp);

    if (PASS == 1) {
        float sl, sh, ql, qh;
        upk2(s2, sl, sh); upk2(q2, ql, qh);
        float s = sl + sh, q = ql + qh;
        #pragma unroll
        for (int off = 16; off > 0; off >>= 1) {
            s += __shfl_down_sync(0xffffffffu, s, off);
            q += __shfl_down_sync(0xffffffffu, q, off);
        }
        __syncthreads();                 // compute done; smem reusable
        float* red = (float*)smem4;
        const int warp = tid >> 5;
        if (lane == 0) { red[warp] = s; red[8 + warp] = q; }
        __syncthreads();
        if (tid == 0) {
            g_psum[bc * NCHUNK + hc] = red[0] + red[1] + red[2] + red[3];
            g_psq [bc * NCHUNK + hc] = red[8] + red[9] + red[10] + red[11];
        }
    }
}

__global__ void finalize_stats_kernel()
{
    const int bc = threadIdx.x;
    if (bc >= BC) return;
    double s = 0.0, q = 0.0;
    #pragma unroll
    for (int j = 0; j < NCHUNK; ++j) {
        s += (double)g_psum[bc * NCHUNK + j];
        q += (double)g_psq [bc * NCHUNK + j];
    }
    const double n = (double)SLAB;
    const double mean = s / n;
    const double var  = q / n - mean * mean;
    g_mean[bc] = (float)mean;
    g_rstd[bc] = (float)(1.0 / sqrt(var + 1e-5));
}

extern "C" void kernel_launch(void* const* d_in, const int* in_sizes, int n_in,
                              void* d_out, int out_size)
{
    (void)in_sizes; (void)n_in; (void)out_size;
    const float* x     = (const float*)d_in[0];
    const float* w     = (const float*)d_in[1];
    const float* gamma = (const float*)d_in[2];
    const float* beta  = (const float*)d_in[3];
    float* out = (float*)d_out;

    dim3 grid(NCHUNK, BC);  // 1024 CTAs of 128 threads; 4 CTAs/SM (smem 110KB, regs<=125)
    conv_stream_kernel<1><<<grid, NTHR, SMEM_BYTES>>>(x, w, gamma, beta, out);
    finalize_stats_kernel<<<1, BC>>>();
    conv_stream_kernel<2><<<grid, NTHR, SMEM_BYTES>>>(x, w, gamma, beta, out);
}